// round 7
// baseline (speedup 1.0000x reference)
#include <cuda_runtime.h>
#include <math_constants.h>

#define BB 64
#define JJ 32
#define MM 160
#define NN 160
#define HW (MM * NN)   // 25600
#define THREADS 256
#define NWARP (THREADS / 32)
#define NOBJ (BB * JJ) // 2048

__device__ float g_perobj[NOBJ];
__device__ unsigned int g_count = 0;

// Fused: per-(b,j) argmax over 25600 floats + loss computation + last-block
// final batch reduction (no second kernel launch, no per-block L1 flush).
__global__ __launch_bounds__(THREADS) void argmax_loss_fused_kernel(
    const float* __restrict__ pred,
    const float* __restrict__ gt,
    const float* __restrict__ heatmap,
    float* __restrict__ out)
{
    const int bj = blockIdx.x;                 // 0 .. B*J-1
    const int tid = threadIdx.x;
    const float4* row = reinterpret_cast<const float4*>(heatmap + (size_t)bj * HW);

    float best = -CUDART_INF_F;
    int bidx = 0;

    // 6400 float4 per row; 256 threads -> 25 iterations each.
    // Moderate unroll: ~5 loads in flight per warp, serial comparator chain.
    // (Full 25-deep front-batching measured SLOWER: L1tex queue contention.)
    #pragma unroll 5
    for (int i = tid; i < HW / 4; i += THREADS) {
        float4 v = row[i];
        int base = i * 4;
        // strictly-greater keeps the earliest index within a thread
        if (v.x > best) { best = v.x; bidx = base; }
        if (v.y > best) { best = v.y; bidx = base + 1; }
        if (v.z > best) { best = v.z; bidx = base + 2; }
        if (v.w > best) { best = v.w; bidx = base + 3; }
    }

    // Warp-level reduction (no barriers): 5 shfl steps on (val, idx) pairs.
    #pragma unroll
    for (int off = 16; off > 0; off >>= 1) {
        float ov = __shfl_down_sync(0xFFFFFFFFu, best, off);
        int   oi = __shfl_down_sync(0xFFFFFFFFu, bidx, off);
        if (ov > best || (ov == best && oi < bidx)) { best = ov; bidx = oi; }
    }

    __shared__ float svals[NWARP];
    __shared__ int   sidx[NWARP];
    const int warp = tid >> 5;
    const int lane = tid & 31;
    if (lane == 0) { svals[warp] = best; sidx[warp] = bidx; }
    __syncthreads();

    // Warps 1..7 are done: retire early, only warp 0 runs the tail.
    if (warp != 0) return;

    // Merge the 8 warp winners in-warp (lanes 0..7 hold candidates).
    {
        float mv = (lane < NWARP) ? svals[lane] : -CUDART_INF_F;
        int   mi = (lane < NWARP) ? sidx[lane]  : 0x7FFFFFFF;
        #pragma unroll
        for (int off = 4; off > 0; off >>= 1) {
            float ov = __shfl_down_sync(0xFFFFFFFFu, mv, off);
            int   oi = __shfl_down_sync(0xFFFFFFFFu, mi, off);
            if (ov > mv || (ov == mv && oi < mi)) { mv = ov; mi = oi; }
        }
        best = mv;
        bidx = mi;
    }

    unsigned int old = 0;
    if (lane == 0) {
        int idx = bidx;
        float x = (float)(idx / MM);   // reference: idx // m
        float y = (float)(idx % MM);   // reference: idx %  m

        int b = bj / JJ;
        int j = bj % JJ;

        const float* g = gt + ((size_t)b * JJ + j) * 11;
        float g7 = g[7], g8 = g[8], g9 = g[9], g10 = g[10];
        bool valid = (g9 > 0.0f) && (g10 > 0.0f) && (g9 < (float)MM) && (g10 < (float)NN);

        // pred layout: (B, 9, J, 1) -> pred[((b*9 + c)*J) + j]
        const float* pb = pred + (size_t)b * 9 * JJ + j;
        float px = pb[7 * JJ];
        float py = pb[8 * JJ];

        float dx = g9 + g7 - x - px;
        float dy = g10 + g8 - y - py;
        float loss = dx * dx + dy * dy;

        float cls = 0.0f;
        #pragma unroll
        for (int c = 0; c < 7; c++) {
            float d = pb[c * JJ] - g[c];
            cls = fmaf(d, d, cls);
        }

        g_perobj[bj] = valid ? (cls + loss) : 0.0f;

        // Release-atomic: orders the g_perobj store before the count bump
        // WITHOUT the CCTL.IVALL L1-flush that __threadfence() would emit.
        asm volatile("atom.release.gpu.add.u32 %0, [%1], 1;"
                     : "=r"(old) : "l"(&g_count) : "memory");
    }
    old = __shfl_sync(0xFFFFFFFFu, old, 0);

    if (old == NOBJ - 1) {
        // Last block: acquire side (one fence per LAUNCH, not per block).
        __threadfence();
        // 32 lanes each sum 2 batches of 32 per-joint losses.
        #pragma unroll
        for (int r = 0; r < 2; r++) {
            int b = lane * 2 + r;
            float s = 0.0f;
            #pragma unroll
            for (int j = 0; j < JJ; j++)
                s += __ldcg(&g_perobj[b * JJ + j]);
            out[b] = s;
        }
        if (lane == 0)
            g_count = 0;   // reset for next graph replay (deterministic)
    }
}

extern "C" void kernel_launch(void* const* d_in, const int* in_sizes, int n_in,
                              void* d_out, int out_size)
{
    const float* pred    = (const float*)d_in[0];
    const float* gt      = (const float*)d_in[1];
    const float* heatmap = (const float*)d_in[2];
    float* out = (float*)d_out;

    argmax_loss_fused_kernel<<<NOBJ, THREADS>>>(pred, gt, heatmap, out);
}

// round 8
// speedup vs baseline: 1.0008x; 1.0008x over previous
#include <cuda_runtime.h>
#include <math_constants.h>

#define BB 64
#define JJ 32
#define MM 160
#define NN 160
#define HW (MM * NN)   // 25600
#define THREADS 128
#define NWARP (THREADS / 32)   // 4
#define NOBJ (BB * JJ) // 2048

__device__ float g_perobj[NOBJ];
__device__ unsigned int g_count = 0;

// Fused: per-(b,j) argmax over 25600 floats + loss computation + last-block
// final batch reduction. 128-thread blocks, 14 blocks/SM -> the whole grid
// (2048 CTAs <= 148*14 = 2072 slots) is a SINGLE wave: no wave transition,
// no late-wave tail.
__global__ __launch_bounds__(THREADS, 14) void argmax_loss_fused_kernel(
    const float* __restrict__ pred,
    const float* __restrict__ gt,
    const float* __restrict__ heatmap,
    float* __restrict__ out)
{
    const int bj = blockIdx.x;                 // 0 .. B*J-1
    const int tid = threadIdx.x;
    const float4* row = reinterpret_cast<const float4*>(heatmap + (size_t)bj * HW);

    float best = -CUDART_INF_F;
    int bidx = 0;

    // 6400 float4 per row; 128 threads -> 50 iterations each.
    // Moderate unroll: ~5 loads in flight per warp, serial comparator chain.
    #pragma unroll 5
    for (int i = tid; i < HW / 4; i += THREADS) {
        float4 v = row[i];
        int base = i * 4;
        // strictly-greater keeps the earliest index within a thread
        if (v.x > best) { best = v.x; bidx = base; }
        if (v.y > best) { best = v.y; bidx = base + 1; }
        if (v.z > best) { best = v.z; bidx = base + 2; }
        if (v.w > best) { best = v.w; bidx = base + 3; }
    }

    // Warp-level reduction (no barriers): 5 shfl steps on (val, idx) pairs.
    #pragma unroll
    for (int off = 16; off > 0; off >>= 1) {
        float ov = __shfl_down_sync(0xFFFFFFFFu, best, off);
        int   oi = __shfl_down_sync(0xFFFFFFFFu, bidx, off);
        if (ov > best || (ov == best && oi < bidx)) { best = ov; bidx = oi; }
    }

    __shared__ float svals[NWARP];
    __shared__ int   sidx[NWARP];
    const int warp = tid >> 5;
    const int lane = tid & 31;
    if (lane == 0) { svals[warp] = best; sidx[warp] = bidx; }
    __syncthreads();

    // Warps 1..3 are done: retire early, only warp 0 runs the tail.
    if (warp != 0) return;

    // Merge the 4 warp winners in-warp (lanes 0..3 hold candidates).
    {
        float mv = (lane < NWARP) ? svals[lane] : -CUDART_INF_F;
        int   mi = (lane < NWARP) ? sidx[lane]  : 0x7FFFFFFF;
        #pragma unroll
        for (int off = 2; off > 0; off >>= 1) {
            float ov = __shfl_down_sync(0xFFFFFFFFu, mv, off);
            int   oi = __shfl_down_sync(0xFFFFFFFFu, mi, off);
            if (ov > mv || (ov == mv && oi < mi)) { mv = ov; mi = oi; }
        }
        best = mv;
        bidx = mi;
    }

    unsigned int old = 0;
    if (lane == 0) {
        int idx = bidx;
        float x = (float)(idx / MM);   // reference: idx // m
        float y = (float)(idx % MM);   // reference: idx %  m

        int b = bj / JJ;
        int j = bj % JJ;

        const float* g = gt + ((size_t)b * JJ + j) * 11;
        float g7 = g[7], g8 = g[8], g9 = g[9], g10 = g[10];
        bool valid = (g9 > 0.0f) && (g10 > 0.0f) && (g9 < (float)MM) && (g10 < (float)NN);

        // pred layout: (B, 9, J, 1) -> pred[((b*9 + c)*J) + j]
        const float* pb = pred + (size_t)b * 9 * JJ + j;
        float px = pb[7 * JJ];
        float py = pb[8 * JJ];

        float dx = g9 + g7 - x - px;
        float dy = g10 + g8 - y - py;
        float loss = dx * dx + dy * dy;

        float cls = 0.0f;
        #pragma unroll
        for (int c = 0; c < 7; c++) {
            float d = pb[c * JJ] - g[c];
            cls = fmaf(d, d, cls);
        }

        g_perobj[bj] = valid ? (cls + loss) : 0.0f;

        // Release-atomic: orders the g_perobj store before the count bump
        // without a per-block L1-flushing __threadfence().
        asm volatile("atom.release.gpu.add.u32 %0, [%1], 1;"
                     : "=r"(old) : "l"(&g_count) : "memory");
    }
    old = __shfl_sync(0xFFFFFFFFu, old, 0);

    if (old == NOBJ - 1) {
        // Last block: acquire side (one fence per LAUNCH, not per block).
        __threadfence();
        // 32 lanes each sum 2 batches of 32 per-joint losses.
        #pragma unroll
        for (int r = 0; r < 2; r++) {
            int b = lane * 2 + r;
            float s = 0.0f;
            #pragma unroll
            for (int j = 0; j < JJ; j++)
                s += __ldcg(&g_perobj[b * JJ + j]);
            out[b] = s;
        }
        if (lane == 0)
            g_count = 0;   // reset for next graph replay (deterministic)
    }
}

extern "C" void kernel_launch(void* const* d_in, const int* in_sizes, int n_in,
                              void* d_out, int out_size)
{
    const float* pred    = (const float*)d_in[0];
    const float* gt      = (const float*)d_in[1];
    const float* heatmap = (const float*)d_in[2];
    float* out = (float*)d_out;

    argmax_loss_fused_kernel<<<NOBJ, THREADS>>>(pred, gt, heatmap, out);
}

// round 9
// speedup vs baseline: 1.0065x; 1.0057x over previous
#include <cuda_runtime.h>
#include <math_constants.h>

#define BB 64
#define JJ 32
#define MM 160
#define NN 160
#define HW (MM * NN)   // 25600
#define THREADS 128
#define NWARP (THREADS / 32)   // 4
#define NOBJ (BB * JJ) // 2048
#define NV4 (HW / 4)           // 6400 float4 per row
#define PAIRS (NV4 / THREADS / 2)  // 25 pair-iterations per thread

__device__ float g_perobj[NOBJ];
__device__ unsigned int g_count = 0;

// Fused: per-(b,j) argmax + loss + last-block reduction, single wave.
// Inner loop uses FMNMX (fmaxf) trees instead of FSETP/select chains:
// one predicated (best, i) update per float4, two independent chains.
__global__ __launch_bounds__(THREADS, 14) void argmax_loss_fused_kernel(
    const float* __restrict__ pred,
    const float* __restrict__ gt,
    const float* __restrict__ heatmap,
    float* __restrict__ out)
{
    const int bj = blockIdx.x;                 // 0 .. B*J-1
    const int tid = threadIdx.x;
    const float4* row = reinterpret_cast<const float4*>(heatmap + (size_t)bj * HW);

    // Two independent chains: even/odd slots. Track float4 index only;
    // the winning element within the float4 is resolved after the loop.
    float best0 = -CUDART_INF_F, best1 = -CUDART_INF_F;
    int   bi0 = 0, bi1 = 0;

    #pragma unroll 5
    for (int m = 0; m < PAIRS; m++) {
        int i0 = tid + (2 * m) * THREADS;
        int i1 = i0 + THREADS;
        float4 v0 = row[i0];
        float4 v1 = row[i1];

        // 2-level fmax tree: 3 FMNMX, no predicates.
        float m0 = fmaxf(fmaxf(v0.x, v0.y), fmaxf(v0.z, v0.w));
        float m1 = fmaxf(fmaxf(v1.x, v1.y), fmaxf(v1.z, v1.w));

        // strict > keeps earliest float4 on ties (i grows with m)
        if (m0 > best0) { best0 = m0; bi0 = i0; }
        if (m1 > best1) { best1 = m1; bi1 = i1; }
    }

    // Merge chains: chains own disjoint i sets; tie -> smaller float4 index.
    float best = best0;
    int   bi   = bi0;
    if (best1 > best || (best1 == best && bi1 < bi)) { best = best1; bi = bi1; }

    // Resolve element within the winning float4 (first equal wins).
    // fmaxf returned one of the loaded values bit-exactly, so == matches.
    int bidx;
    {
        float4 v = row[bi];
        int e = 3;
        if (v.z == best) e = 2;
        if (v.y == best) e = 1;
        if (v.x == best) e = 0;
        bidx = bi * 4 + e;
    }

    // Warp-level reduction: 5 shfl steps on (val, idx) pairs.
    #pragma unroll
    for (int off = 16; off > 0; off >>= 1) {
        float ov = __shfl_down_sync(0xFFFFFFFFu, best, off);
        int   oi = __shfl_down_sync(0xFFFFFFFFu, bidx, off);
        if (ov > best || (ov == best && oi < bidx)) { best = ov; bidx = oi; }
    }

    __shared__ float svals[NWARP];
    __shared__ int   sidx[NWARP];
    const int warp = tid >> 5;
    const int lane = tid & 31;
    if (lane == 0) { svals[warp] = best; sidx[warp] = bidx; }
    __syncthreads();

    // Warps 1..3 retire; warp 0 runs the tail.
    if (warp != 0) return;

    {
        float mv = (lane < NWARP) ? svals[lane] : -CUDART_INF_F;
        int   mi = (lane < NWARP) ? sidx[lane]  : 0x7FFFFFFF;
        #pragma unroll
        for (int off = 2; off > 0; off >>= 1) {
            float ov = __shfl_down_sync(0xFFFFFFFFu, mv, off);
            int   oi = __shfl_down_sync(0xFFFFFFFFu, mi, off);
            if (ov > mv || (ov == mv && oi < mi)) { mv = ov; mi = oi; }
        }
        best = mv;
        bidx = mi;
    }

    unsigned int old = 0;
    if (lane == 0) {
        int idx = bidx;
        float x = (float)(idx / MM);   // reference: idx // m
        float y = (float)(idx % MM);   // reference: idx %  m

        int b = bj / JJ;
        int j = bj % JJ;

        const float* g = gt + ((size_t)b * JJ + j) * 11;
        float g7 = g[7], g8 = g[8], g9 = g[9], g10 = g[10];
        bool valid = (g9 > 0.0f) && (g10 > 0.0f) && (g9 < (float)MM) && (g10 < (float)NN);

        // pred layout: (B, 9, J, 1) -> pred[((b*9 + c)*J) + j]
        const float* pb = pred + (size_t)b * 9 * JJ + j;
        float px = pb[7 * JJ];
        float py = pb[8 * JJ];

        float dx = g9 + g7 - x - px;
        float dy = g10 + g8 - y - py;
        float loss = dx * dx + dy * dy;

        float cls = 0.0f;
        #pragma unroll
        for (int c = 0; c < 7; c++) {
            float d = pb[c * JJ] - g[c];
            cls = fmaf(d, d, cls);
        }

        g_perobj[bj] = valid ? (cls + loss) : 0.0f;

        // Release-atomic: orders the g_perobj store before the count bump
        // without a per-block L1-flushing __threadfence().
        asm volatile("atom.release.gpu.add.u32 %0, [%1], 1;"
                     : "=r"(old) : "l"(&g_count) : "memory");
    }
    old = __shfl_sync(0xFFFFFFFFu, old, 0);

    if (old == NOBJ - 1) {
        // Last block: acquire side (one fence per LAUNCH, not per block).
        __threadfence();
        // 32 lanes each sum 2 batches of 32 per-joint losses.
        #pragma unroll
        for (int r = 0; r < 2; r++) {
            int b = lane * 2 + r;
            float s = 0.0f;
            #pragma unroll
            for (int j = 0; j < JJ; j++)
                s += __ldcg(&g_perobj[b * JJ + j]);
            out[b] = s;
        }
        if (lane == 0)
            g_count = 0;   // reset for next graph replay (deterministic)
    }
}

extern "C" void kernel_launch(void* const* d_in, const int* in_sizes, int n_in,
                              void* d_out, int out_size)
{
    const float* pred    = (const float*)d_in[0];
    const float* gt      = (const float*)d_in[1];
    const float* heatmap = (const float*)d_in[2];
    float* out = (float*)d_out;

    argmax_loss_fused_kernel<<<NOBJ, THREADS>>>(pred, gt, heatmap, out);
}